// round 16
// baseline (speedup 1.0000x reference)
#include <cuda_runtime.h>
#include <cstdint>

// Problem shape
#define BDIM   8192
#define DDIM   2048
#define NUNITS 2048
#define KW     64          // 2048 bits = 64 u32 words per row

// A bits: [128-row tile][j][rowInTile] ; B bits: [64-col tile][j][colInTile]
__device__ __align__(128) uint32_t g_Abits[(size_t)(BDIM / 128) * KW * 128];   // 2 MB
__device__ __align__(128) uint32_t g_Bbits[(size_t)(NUNITS / 64) * KW * 64];   // 512 KB

// ============================ Merged pack kernel ============================
#define PACKA_BLOCKS 4096

__global__ void __launch_bounds__(256) pack_all(
    const float* __restrict__ in, const float* __restrict__ kern,
    uint32_t* __restrict__ abits, uint32_t* __restrict__ bbits)
{
    __shared__ uint8_t tile[128 * 33];        // only used by B role
    const int tid = threadIdx.x;

    if (blockIdx.x < PACKA_BLOCKS) {
        // ---- A role: warp per (row, 4 segs of 128 k) ----
        int lane = tid & 31;
        int warp = (blockIdx.x * 256 + tid) >> 5;
        int m   = warp >> 2;
        int sg0 = (warp & 3) * 4;

        float4 v[4];
#pragma unroll
        for (int s = 0; s < 4; s++)
            v[s] = *(const float4*)&in[(size_t)m * DDIM + (sg0 + s) * 128 + lane * 4];

        uint32_t* base = abits + (size_t)(m >> 7) * (KW * 128) + (m & 127);
#pragma unroll
        for (int s = 0; s < 4; s++) {
            int j0 = (sg0 + s) * 4;
            uint32_t w0 = __ballot_sync(0xFFFFFFFFu, v[s].x < 0.0f);
            uint32_t w1 = __ballot_sync(0xFFFFFFFFu, v[s].y < 0.0f);
            uint32_t w2 = __ballot_sync(0xFFFFFFFFu, v[s].z < 0.0f);
            uint32_t w3 = __ballot_sync(0xFFFFFFFFu, v[s].w < 0.0f);
            if (lane == 0) {
                base[(j0 + 0) * 128] = w0;
                base[(j0 + 1) * 128] = w1;
                base[(j0 + 2) * 128] = w2;
                base[(j0 + 3) * 128] = w3;
            }
        }
    } else {
        // ---- B role: word j = 4*by + q, bit l = sign(kern[128*by + 4l + q][n]) ----
        int bid = blockIdx.x - PACKA_BLOCKS;
        int n0 = (bid & 63) * 32;
        int by = bid >> 6;
        int kb = by * 128;
        int tx = tid & 31, ty = tid >> 5;     // (32, 8)
#pragma unroll
        for (int s = 0; s < 16; s++) {
            int k = ty + s * 8;
            float v = kern[(size_t)(kb + k) * NUNITS + n0 + tx];
            tile[k * 33 + tx] = (v < 0.0f) ? 1 : 0;
        }
        __syncthreads();

        int lane = tx;                        // warp = ty
#pragma unroll
        for (int nl = 0; nl < 4; nl++) {
            int n = n0 + ty * 4 + nl;
            uint32_t* dst = bbits + (size_t)(n >> 6) * (KW * 64) + (n & 63);
#pragma unroll
            for (int q = 0; q < 4; q++) {
                uint8_t val = tile[(4 * lane + q) * 33 + (ty * 4 + nl)];
                uint32_t word = __ballot_sync(0xFFFFFFFFu, val != 0);
                if (lane == 0)
                    dst[(by * 4 + q) * 64] = word;
            }
        }
    }
}

// ============================ popcount GEMM ============================
// 128x64 tile, 512 threads, per-thread 4x4. RAW XOR->POPC->IMAD (no CSA):
// identical instruction count per word-pair as CSA but 1/3 the operand regs,
// enabling 3 CTAs/SM (42-reg cap) = 12 warps/SMSP (70% occ).
// out[m][n] = 2048 - 2 * sum_j popc(A[m][j] ^ B[n][j]) + bias[n]

__global__ void __launch_bounds__(512, 3) popc_gemm(
    const uint32_t* __restrict__ Ab, const uint32_t* __restrict__ Bb,
    const float* __restrict__ bias, float* __restrict__ out)
{
    extern __shared__ uint32_t smem[];        // A 8192 words, B 4096 words, k1
    uint32_t* Asm = smem;
    uint32_t* Bsm = smem + KW * 128;
    int* ksm = (int*)(smem + KW * 128 + KW * 64);

    const int tid = threadIdx.x;
    const int nblk = blockIdx.x, mblk = blockIdx.y;

    if (tid == 0) ksm[0] = 1;

    {
        const uint4* gA = (const uint4*)(Ab + (size_t)mblk * (KW * 128));
        uint4* sA = (uint4*)Asm;
#pragma unroll
        for (int i = 0; i < 4; i++)
            sA[tid + i * 512] = gA[tid + i * 512];
        const uint4* gB = (const uint4*)(Bb + (size_t)nblk * (KW * 64));
        uint4* sB = (uint4*)Bsm;
#pragma unroll
        for (int i = 0; i < 2; i++)
            sB[tid + i * 512] = gB[tid + i * 512];
    }
    __syncthreads();

    const int k1 = ksm[0];                    // == 1, opaque -> IMAD on fma pipe
    const int tx = tid & 15;                  // 16 n-subblocks x 4 cols
    const int ty = tid >> 4;                  // 32 m-subblocks x 4 rows

    int acc[4][4];
#pragma unroll
    for (int i = 0; i < 4; i++)
#pragma unroll
        for (int k = 0; k < 4; k++) acc[i][k] = 0;

    const uint32_t* Ap = &Asm[ty * 4];
    const uint32_t* Bp = &Bsm[tx * 4];
#pragma unroll 4
    for (int j = 0; j < KW; j++) {
        uint32_t a[4], b[4];
        *(uint4*)&a[0] = *(const uint4*)&Ap[j * 128];
        *(uint4*)&b[0] = *(const uint4*)&Bp[j * 64];
#pragma unroll
        for (int mi = 0; mi < 4; mi++) {
#pragma unroll
            for (int ni = 0; ni < 4; ni++)
                acc[mi][ni] = __popc(a[mi] ^ b[ni]) * k1 + acc[mi][ni];
        }
    }

    // epilogue: val = 2048 - 2*acc + bias
    const int n0 = nblk * 64 + tx * 4;
    float bl[4];
    *(float4*)&bl[0] = *(const float4*)&bias[n0];
#pragma unroll
    for (int i = 0; i < 4; i++) bl[i] += 2048.0f;

#pragma unroll
    for (int mi = 0; mi < 4; mi++) {
        size_t row = (size_t)(mblk * 128 + ty * 4 + mi) * NUNITS + n0;
        float4 v0;
        v0.x = fmaf(-2.0f, (float)acc[mi][0], bl[0]);
        v0.y = fmaf(-2.0f, (float)acc[mi][1], bl[1]);
        v0.z = fmaf(-2.0f, (float)acc[mi][2], bl[2]);
        v0.w = fmaf(-2.0f, (float)acc[mi][3], bl[3]);
        *(float4*)&out[row] = v0;
    }
}

// ============================ Host ============================

#define GEMM_SMEM ((KW * 128 + KW * 64) * 4 + 16)   // 48 KB + k1 -> 3 CTAs/SM (144 KB)

extern "C" void kernel_launch(void* const* d_in, const int* in_sizes, int n_in,
                              void* d_out, int out_size) {
    const float* inputs = (const float*)d_in[0];
    const float* kern   = (const float*)d_in[1];
    const float* bias   = (const float*)d_in[2];
    float* out = (float*)d_out;

    void *pA = nullptr, *pB = nullptr;
    cudaGetSymbolAddress(&pA, g_Abits);
    cudaGetSymbolAddress(&pB, g_Bbits);

    // 1) merged packs: one launch
    pack_all<<<PACKA_BLOCKS + 1024, 256>>>(inputs, kern, (uint32_t*)pA, (uint32_t*)pB);

    // 2) raw popcount GEMM: 128x64 tiles, 512 threads, 3 CTAs/SM (36 warps)
    cudaFuncSetAttribute(popc_gemm, cudaFuncAttributeMaxDynamicSharedMemorySize, GEMM_SMEM);
    dim3 grid(NUNITS / 64, BDIM / 128);        // (32, 64) = 2048 CTAs
    popc_gemm<<<grid, 512, GEMM_SMEM>>>((const uint32_t*)pA, (const uint32_t*)pB, bias, out);
}

// round 17
// speedup vs baseline: 1.2074x; 1.2074x over previous
#include <cuda_runtime.h>
#include <cstdint>

// Problem shape
#define BDIM   8192
#define DDIM   2048
#define NUNITS 2048
#define KW     64          // 2048 bits = 64 u32 words per row

// A bits: [128-row tile][j][rowInTile] ; B bits: [64-col tile][j][colInTile]
__device__ __align__(128) uint32_t g_Abits[(size_t)(BDIM / 128) * KW * 128];   // 2 MB
__device__ __align__(128) uint32_t g_Bbits[(size_t)(NUNITS / 64) * KW * 64];   // 512 KB

// ============================ Merged pack kernel ============================
#define PACKA_BLOCKS 4096

__global__ void __launch_bounds__(256) pack_all(
    const float* __restrict__ in, const float* __restrict__ kern,
    uint32_t* __restrict__ abits, uint32_t* __restrict__ bbits)
{
    __shared__ uint8_t tile[128 * 33];        // only used by B role
    const int tid = threadIdx.x;

    if (blockIdx.x < PACKA_BLOCKS) {
        // ---- A role: warp per (row, 4 segs of 128 k) ----
        int lane = tid & 31;
        int warp = (blockIdx.x * 256 + tid) >> 5;
        int m   = warp >> 2;
        int sg0 = (warp & 3) * 4;

        float4 v[4];
#pragma unroll
        for (int s = 0; s < 4; s++)
            v[s] = *(const float4*)&in[(size_t)m * DDIM + (sg0 + s) * 128 + lane * 4];

        uint32_t* base = abits + (size_t)(m >> 7) * (KW * 128) + (m & 127);
#pragma unroll
        for (int s = 0; s < 4; s++) {
            int j0 = (sg0 + s) * 4;
            uint32_t w0 = __ballot_sync(0xFFFFFFFFu, v[s].x < 0.0f);
            uint32_t w1 = __ballot_sync(0xFFFFFFFFu, v[s].y < 0.0f);
            uint32_t w2 = __ballot_sync(0xFFFFFFFFu, v[s].z < 0.0f);
            uint32_t w3 = __ballot_sync(0xFFFFFFFFu, v[s].w < 0.0f);
            if (lane == 0) {
                base[(j0 + 0) * 128] = w0;
                base[(j0 + 1) * 128] = w1;
                base[(j0 + 2) * 128] = w2;
                base[(j0 + 3) * 128] = w3;
            }
        }
    } else {
        // ---- B role: word j = 4*by + q, bit l = sign(kern[128*by + 4l + q][n]) ----
        int bid = blockIdx.x - PACKA_BLOCKS;
        int n0 = (bid & 63) * 32;
        int by = bid >> 6;
        int kb = by * 128;
        int tx = tid & 31, ty = tid >> 5;     // (32, 8)
#pragma unroll
        for (int s = 0; s < 16; s++) {
            int k = ty + s * 8;
            float v = kern[(size_t)(kb + k) * NUNITS + n0 + tx];
            tile[k * 33 + tx] = (v < 0.0f) ? 1 : 0;
        }
        __syncthreads();

        int lane = tx;                        // warp = ty
#pragma unroll
        for (int nl = 0; nl < 4; nl++) {
            int n = n0 + ty * 4 + nl;
            uint32_t* dst = bbits + (size_t)(n >> 6) * (KW * 64) + (n & 63);
#pragma unroll
            for (int q = 0; q < 4; q++) {
                uint8_t val = tile[(4 * lane + q) * 33 + (ty * 4 + nl)];
                uint32_t word = __ballot_sync(0xFFFFFFFFu, val != 0);
                if (lane == 0)
                    dst[(by * 4 + q) * 64] = word;
            }
        }
    }
}

// ============================ Harley-Seal popcount GEMM ============================
// Per (mi,ni) pair keep a 'ones' carry-save register. Per 2 k-words:
//   x0 = a0^b0 ; x1 = a1^b1                (alu: 2 XOR)
//   carry = maj(ones, x0, x1)              (alu: 1 LOP3)
//   ones  = ones ^ x0 ^ x1                 (alu: 1 LOP3)
//   acc  += 2 * popc(carry)                (popc pipe + IMAD on fma)
// Finally acc += popc(ones). POPC count: 0.5/word (vs 0.69 CSA, 1.0 raw) —
// POPC is the quarter-rate pipe (measured 2 cyc/SM), so this balances
// popc-pipe (1.0 SM-cyc/pair-word) against alu (1.0 SM-cyc/pair-word).
// out[m][n] = 2048 - 2 * sum_j popc(A^B) + bias[n]

__global__ void __launch_bounds__(512, 2) popc_gemm(
    const uint32_t* __restrict__ Ab, const uint32_t* __restrict__ Bb,
    const float* __restrict__ bias, float* __restrict__ out)
{
    extern __shared__ uint32_t smem[];        // A 8192 words, B 4096 words, k1/k2
    uint32_t* Asm = smem;
    uint32_t* Bsm = smem + KW * 128;
    int* ksm = (int*)(smem + KW * 128 + KW * 64);

    const int tid = threadIdx.x;
    const int nblk = blockIdx.x, mblk = blockIdx.y;

    if (tid == 0) { ksm[0] = 1; ksm[1] = 2; }

    {
        const uint4* gA = (const uint4*)(Ab + (size_t)mblk * (KW * 128));
        uint4* sA = (uint4*)Asm;
#pragma unroll
        for (int i = 0; i < 4; i++)
            sA[tid + i * 512] = gA[tid + i * 512];
        const uint4* gB = (const uint4*)(Bb + (size_t)nblk * (KW * 64));
        uint4* sB = (uint4*)Bsm;
#pragma unroll
        for (int i = 0; i < 2; i++)
            sB[tid + i * 512] = gB[tid + i * 512];
    }
    __syncthreads();

    const int k1 = ksm[0];                    // == 1, opaque -> IMAD on fma pipe
    const int k2 = ksm[1];                    // == 2, opaque
    const int tx = tid & 15;                  // 16 n-subblocks x 4 cols
    const int ty = tid >> 4;                  // 32 m-subblocks x 4 rows

    int acc[4][4];
    uint32_t ones[4][4];
#pragma unroll
    for (int i = 0; i < 4; i++)
#pragma unroll
        for (int k = 0; k < 4; k++) { acc[i][k] = 0; ones[i][k] = 0u; }

    const uint32_t* Ap = &Asm[ty * 4];
    const uint32_t* Bp = &Bsm[tx * 4];

#pragma unroll 2
    for (int jp = 0; jp < KW / 2; jp++) {
        uint32_t a0[4], a1[4], b0[4], b1[4];
        *(uint4*)&a0[0] = *(const uint4*)&Ap[(2 * jp) * 128];
        *(uint4*)&a1[0] = *(const uint4*)&Ap[(2 * jp + 1) * 128];
        *(uint4*)&b0[0] = *(const uint4*)&Bp[(2 * jp) * 64];
        *(uint4*)&b1[0] = *(const uint4*)&Bp[(2 * jp + 1) * 64];
#pragma unroll
        for (int mi = 0; mi < 4; mi++) {
#pragma unroll
            for (int ni = 0; ni < 4; ni++) {
                uint32_t x0 = a0[mi] ^ b0[ni];                      // XOR
                uint32_t x1 = a1[mi] ^ b1[ni];                      // XOR
                uint32_t o  = ones[mi][ni];
                uint32_t carry = (o & x0) | (x1 & (o | x0));        // LOP3 maj
                ones[mi][ni]   = o ^ x0 ^ x1;                       // LOP3 0x96
                acc[mi][ni] = __popc(carry) * k2 + acc[mi][ni];     // POPC + IMAD
            }
        }
    }
    // fold in the surviving ones-bits (weight 1)
#pragma unroll
    for (int mi = 0; mi < 4; mi++)
#pragma unroll
        for (int ni = 0; ni < 4; ni++)
            acc[mi][ni] = __popc(ones[mi][ni]) * k1 + acc[mi][ni];

    // epilogue: val = 2048 - 2*acc + bias
    const int n0 = nblk * 64 + tx * 4;
    float bl[4];
    *(float4*)&bl[0] = *(const float4*)&bias[n0];
#pragma unroll
    for (int i = 0; i < 4; i++) bl[i] += 2048.0f;

#pragma unroll
    for (int mi = 0; mi < 4; mi++) {
        size_t row = (size_t)(mblk * 128 + ty * 4 + mi) * NUNITS + n0;
        float4 v0;
        v0.x = fmaf(-2.0f, (float)acc[mi][0], bl[0]);
        v0.y = fmaf(-2.0f, (float)acc[mi][1], bl[1]);
        v0.z = fmaf(-2.0f, (float)acc[mi][2], bl[2]);
        v0.w = fmaf(-2.0f, (float)acc[mi][3], bl[3]);
        *(float4*)&out[row] = v0;
    }
}

// ============================ Host ============================

#define GEMM_SMEM ((KW * 128 + KW * 64) * 4 + 16)   // 48 KB -> 2 CTAs/SM

extern "C" void kernel_launch(void* const* d_in, const int* in_sizes, int n_in,
                              void* d_out, int out_size) {
    const float* inputs = (const float*)d_in[0];
    const float* kern   = (const float*)d_in[1];
    const float* bias   = (const float*)d_in[2];
    float* out = (float*)d_out;

    void *pA = nullptr, *pB = nullptr;
    cudaGetSymbolAddress(&pA, g_Abits);
    cudaGetSymbolAddress(&pB, g_Bbits);

    // 1) merged packs: one launch
    pack_all<<<PACKA_BLOCKS + 1024, 256>>>(inputs, kern, (uint32_t*)pA, (uint32_t*)pB);

    // 2) Harley-Seal popcount GEMM: 128x64 tiles, 512 threads, 2 CTAs/SM
    cudaFuncSetAttribute(popc_gemm, cudaFuncAttributeMaxDynamicSharedMemorySize, GEMM_SMEM);
    dim3 grid(NUNITS / 64, BDIM / 128);        // (32, 64) = 2048 CTAs
    popc_gemm<<<grid, 512, GEMM_SMEM>>>((const uint32_t*)pA, (const uint32_t*)pB, bias, out);
}